// round 5
// baseline (speedup 1.0000x reference)
#include <cuda_runtime.h>
#include <cuda_bf16.h>

#define TPB 256

// Segments are uniform & contiguous (generator: b=repeat(arange(B)), s=tile(arange(S)),
// g=s//span) -> nnz entry r sources feats row r exactly (b*S+s == r). We issue feats
// loads speculatively with that identity map (pure arithmetic, so they pipeline with
// NO dependencies), then verify against the real index data loaded concurrently and
// reload on mismatch. Persistent CTAs stream a blocked range of segment-pairs with a
// 2-stage pipeline so the LSU never drains.
__global__ void __launch_bounds__(TPB) seg_group_kernel(
    const float4* __restrict__ feats4,
    const int*    __restrict__ idxw,     // int32 word view of the indices buffer
    const float*  __restrict__ values,
    float4*       __restrict__ out4,
    int H, int nnz, int num_segs)
{
    const int cols4 = H >> 2;
    const int span  = nnz / num_segs;

    if (span == 4 && cols4 == TPB && (num_segs & 1) == 0) {
        const int numPairs = num_segs >> 1;
        const int chunk = (numPairs + gridDim.x - 1) / gridDim.x;
        const int p0 = blockIdx.x * chunk;
        const int p1 = min(p0 + chunk, numPairs);
        if (p0 >= p1) return;

        const int c = threadIdx.x;

        // ---- stage 0: speculative feats loads for the first pair (issued FIRST) ----
        float4 x[8];
        {
            const int st = p0 * 8;
            #pragma unroll
            for (int j = 0; j < 8; j++)
                x[j] = __ldcs(&feats4[(st + j) * cols4 + c]);
        }

        // dtype probe (in flight behind the feats loads): int32 word 3*nnz-1 is
        // s_idx[nnz-1]=S-1 (nonzero) for int32, else a zero int64 high-word.
        const bool is32 = (idxw[3LL * nnz - 1] != 0);
        const int lastb = idxw[is32 ? (long long)(nnz - 1) : 2LL * (nnz - 1)];
        const int S = nnz / (lastb + 1);

        for (int p = p0; p < p1; p++) {
            const int st = p * 8;

            // ---- issue NEXT stage's speculative loads before touching this stage ----
            float4 xn[8];
            if (p + 1 < p1) {
                const int stn = (p + 1) * 8;
                #pragma unroll
                for (int j = 0; j < 8; j++)
                    xn[j] = __ldcs(&feats4[(stn + j) * cols4 + c]);
            }

            // ---- verify current stage (index/value loads are L2-resident) ----
            float w[8];
            int   row[8];
            bool  ok = true;
            #pragma unroll
            for (int j = 0; j < 8; j++) {
                const long long pb = st + j;              // b_idx position
                const long long ps = 2LL * nnz + st + j;  // s_idx position
                const int b = idxw[is32 ? pb : 2 * pb];   // little-endian low word
                const int s = idxw[is32 ? ps : 2 * ps];
                w[j]   = values[st + j];
                row[j] = b * S + s;
                ok &= (row[j] == st + j);
            }
            if (!ok) {  // correctness guard; never taken for the generator's data
                #pragma unroll
                for (int j = 0; j < 8; j++)
                    x[j] = __ldcs(&feats4[row[j] * cols4 + c]);
            }

            // ---- reduce + streaming store ----
            float4 a0, a1;
            a0.x = fmaf(w[0], x[0].x, fmaf(w[1], x[1].x, fmaf(w[2], x[2].x, w[3] * x[3].x)));
            a0.y = fmaf(w[0], x[0].y, fmaf(w[1], x[1].y, fmaf(w[2], x[2].y, w[3] * x[3].y)));
            a0.z = fmaf(w[0], x[0].z, fmaf(w[1], x[1].z, fmaf(w[2], x[2].z, w[3] * x[3].z)));
            a0.w = fmaf(w[0], x[0].w, fmaf(w[1], x[1].w, fmaf(w[2], x[2].w, w[3] * x[3].w)));
            a1.x = fmaf(w[4], x[4].x, fmaf(w[5], x[5].x, fmaf(w[6], x[6].x, w[7] * x[7].x)));
            a1.y = fmaf(w[4], x[4].y, fmaf(w[5], x[5].y, fmaf(w[6], x[6].y, w[7] * x[7].y)));
            a1.z = fmaf(w[4], x[4].z, fmaf(w[5], x[5].z, fmaf(w[6], x[6].z, w[7] * x[7].z)));
            a1.w = fmaf(w[4], x[4].w, fmaf(w[5], x[5].w, fmaf(w[6], x[6].w, w[7] * x[7].w)));

            const long long o = (long long)(2 * p) * cols4 + c;
            __stcs(&out4[o],         a0);
            __stcs(&out4[o + cols4], a1);

            #pragma unroll
            for (int j = 0; j < 8; j++) x[j] = xn[j];
        }
        return;
    }

    // ---------------- generic fallback (any span / shapes) ----------------
    const bool is32 = (idxw[3LL * nnz - 1] != 0);
    const int lastb = idxw[is32 ? (long long)(nnz - 1) : 2LL * (nnz - 1)];
    const int S = nnz / (lastb + 1);
    for (int seg = blockIdx.x; seg < num_segs; seg += gridDim.x) {
        const int start = seg * span;
        float4* __restrict__ outRow = out4 + (long long)seg * cols4;
        for (int cc = threadIdx.x; cc < cols4; cc += TPB) {
            float4 acc = make_float4(0.f, 0.f, 0.f, 0.f);
            for (int j = 0; j < span; j++) {
                const long long pb = start + j, ps = 2LL * nnz + start + j;
                const int bb = idxw[is32 ? pb : 2 * pb];
                const int ss = idxw[is32 ? ps : 2 * ps];
                const float wv = values[start + j];
                const float4 xx = feats4[(bb * S + ss) * cols4 + cc];
                acc.x = fmaf(wv, xx.x, acc.x);
                acc.y = fmaf(wv, xx.y, acc.y);
                acc.z = fmaf(wv, xx.z, acc.z);
                acc.w = fmaf(wv, xx.w, acc.w);
            }
            outRow[cc] = acc;
        }
    }
}

extern "C" void kernel_launch(void* const* d_in, const int* in_sizes, int n_in,
                              void* d_out, int out_size)
{
    const float* feats   = (const float*)d_in[0];
    const int*   indices = (const int*)d_in[1];
    const float* values  = (const float*)d_in[2];
    float*       out     = (float*)d_out;

    const int nnz      = in_sizes[2];        // nnz = B*S
    const int H        = in_sizes[0] / nnz;  // feats = B*S*H
    const int num_segs = out_size / H;       // B*G

    // persistent grid: ~4 CTAs per SM, capped by available pairs
    int grid = 592;
    const int numPairs = num_segs / 2;
    if (numPairs > 0 && numPairs < grid) grid = numPairs;
    if (grid < 1) grid = 1;
    seg_group_kernel<<<grid, TPB>>>((const float4*)feats, indices, values,
                                    (float4*)out, H, nnz, num_segs);
}

// round 6
// speedup vs baseline: 1.2465x; 1.2465x over previous
#include <cuda_runtime.h>
#include <cuda_bf16.h>

#define TPB 256

// Segments are uniform & contiguous (generator: b=repeat(arange(B)), s=tile(arange(S)),
// g=s//span) -> nnz entry r sources feats row r exactly (b*S+s == r). We issue the
// 4 feats loads speculatively with that identity map as the CTA's FIRST instructions
// (zero dependent chain), then verify against the real index data (vectorized loads,
// concurrent) and reload on mismatch. One segment per CTA keeps regs low -> high
// occupancy -> staggered CTAs keep the LSU continuously fed.
__global__ void __launch_bounds__(TPB) seg_group_kernel(
    const float4* __restrict__ feats4,
    const int*    __restrict__ idxw,     // int32 word view of the indices buffer
    const float*  __restrict__ values,
    float4*       __restrict__ out4,
    int H, int nnz, int num_segs)
{
    const int cols4 = H >> 2;
    const int span  = nnz / num_segs;
    const int seg   = blockIdx.x;

    if (span == 4 && cols4 == TPB && seg < num_segs) {
        const int c  = threadIdx.x;
        const int st = seg * 4;                  // first nnz row of this segment

        // ---- (1) speculative feats loads: first instructions, no dependencies ----
        float4 x0 = __ldcs(&feats4[(st + 0) * cols4 + c]);
        float4 x1 = __ldcs(&feats4[(st + 1) * cols4 + c]);
        float4 x2 = __ldcs(&feats4[(st + 2) * cols4 + c]);
        float4 x3 = __ldcs(&feats4[(st + 3) * cols4 + c]);

        // ---- (2) concurrent vectorized verification ----
        // dtype probe: int32 word 3*nnz-1 is s_idx[nnz-1]=S-1 (nonzero) for int32
        // buffers, else the zero high-word of a small int64 element.
        const bool is32 = (idxw[3LL * nnz - 1] != 0);
        const float4 wv = *(const float4*)(values + st);

        int4 bv, sv;
        if (is32) {
            bv = *(const int4*)(idxw + st);
            sv = *(const int4*)(idxw + 2LL * nnz + st);
        } else {
            // little-endian: low words at even offsets
            const int4 bl0 = *(const int4*)(idxw + 2LL * st);
            const int4 bl1 = *(const int4*)(idxw + 2LL * st + 4);
            const int4 sl0 = *(const int4*)(idxw + 4LL * nnz + 2LL * st);
            const int4 sl1 = *(const int4*)(idxw + 4LL * nnz + 2LL * st + 4);
            bv = make_int4(bl0.x, bl0.z, bl1.x, bl1.z);
            sv = make_int4(sl0.x, sl0.z, sl1.x, sl1.z);
        }
        const int lastb = idxw[is32 ? (long long)(nnz - 1) : 2LL * (nnz - 1)];
        const int S = nnz / (lastb + 1);

        const int r0 = bv.x * S + sv.x;
        const int r1 = bv.y * S + sv.y;
        const int r2 = bv.z * S + sv.z;
        const int r3 = bv.w * S + sv.w;
        if ((r0 != st) | (r1 != st + 1) | (r2 != st + 2) | (r3 != st + 3)) {
            // correctness guard; never taken for the generator's data
            x0 = __ldcs(&feats4[r0 * cols4 + c]);
            x1 = __ldcs(&feats4[r1 * cols4 + c]);
            x2 = __ldcs(&feats4[r2 * cols4 + c]);
            x3 = __ldcs(&feats4[r3 * cols4 + c]);
        }

        // ---- (3) reduce + streaming store ----
        float4 a;
        a.x = fmaf(wv.x, x0.x, fmaf(wv.y, x1.x, fmaf(wv.z, x2.x, wv.w * x3.x)));
        a.y = fmaf(wv.x, x0.y, fmaf(wv.y, x1.y, fmaf(wv.z, x2.y, wv.w * x3.y)));
        a.z = fmaf(wv.x, x0.z, fmaf(wv.y, x1.z, fmaf(wv.z, x2.z, wv.w * x3.z)));
        a.w = fmaf(wv.x, x0.w, fmaf(wv.y, x1.w, fmaf(wv.z, x2.w, wv.w * x3.w)));

        __stcs(&out4[(long long)seg * cols4 + c], a);
        return;
    }

    // ---------------- generic fallback (any span / shapes) ----------------
    const bool is32 = (idxw[3LL * nnz - 1] != 0);
    const int lastb = idxw[is32 ? (long long)(nnz - 1) : 2LL * (nnz - 1)];
    const int S = nnz / (lastb + 1);
    for (int sg = blockIdx.x; sg < num_segs; sg += gridDim.x) {
        const int start = sg * span;
        float4* __restrict__ outRow = out4 + (long long)sg * cols4;
        for (int cc = threadIdx.x; cc < cols4; cc += TPB) {
            float4 acc = make_float4(0.f, 0.f, 0.f, 0.f);
            for (int j = 0; j < span; j++) {
                const long long pb = start + j, ps = 2LL * nnz + start + j;
                const int bb = idxw[is32 ? pb : 2 * pb];
                const int ss = idxw[is32 ? ps : 2 * ps];
                const float w = values[start + j];
                const float4 xx = feats4[(bb * S + ss) * cols4 + cc];
                acc.x = fmaf(w, xx.x, acc.x);
                acc.y = fmaf(w, xx.y, acc.y);
                acc.z = fmaf(w, xx.z, acc.z);
                acc.w = fmaf(w, xx.w, acc.w);
            }
            outRow[cc] = acc;
        }
    }
}

extern "C" void kernel_launch(void* const* d_in, const int* in_sizes, int n_in,
                              void* d_out, int out_size)
{
    const float* feats   = (const float*)d_in[0];
    const int*   indices = (const int*)d_in[1];
    const float* values  = (const float*)d_in[2];
    float*       out     = (float*)d_out;

    const int nnz      = in_sizes[2];        // nnz = B*S
    const int H        = in_sizes[0] / nnz;  // feats = B*S*H
    const int num_segs = out_size / H;       // B*G

    seg_group_kernel<<<num_segs, TPB>>>((const float4*)feats, indices, values,
                                        (float4*)out, H, nnz, num_segs);
}